// round 10
// baseline (speedup 1.0000x reference)
#include <cuda_runtime.h>
#include <stdint.h>

#define NF     64
#define C      128
#define EF     32
#define MAXN   100000
#define MAXE   1600000
#define BN_EPS 1e-5f

// ---------------- scratch (device globals; no allocations) ----------------
__device__ __align__(16) float g_hsrc[(size_t)MAXN * C];   // 51.2 MB
__device__ __align__(16) float g_hdst[(size_t)MAXN * C];   // 51.2 MB
__device__ __align__(16) float g_m[(size_t)MAXE * C];      // 819 MB
__device__ __align__(16) float g_h[(size_t)MAXN * NF];     // 25.6 MB
__device__ __align__(16) float g_sum[C];
__device__ __align__(16) float g_sumsq[C];
__device__ __align__(16) float g_bn_s[C];
__device__ __align__(16) float g_bn_b[C];
__device__ __align__(16) float g_nsum[NF];
__device__ __align__(16) float g_nsumsq[NF];

// ---------------- packed f32x2 helpers ----------------
typedef unsigned long long u64;
union F4U { float4 f; u64 u[2]; };

__device__ __forceinline__ u64 pack2(float a, float b) {
    u64 r; asm("mov.b64 %0, {%1, %2};" : "=l"(r) : "f"(a), "f"(b)); return r;
}
__device__ __forceinline__ void unpack2(u64 v, float& a, float& b) {
    asm("mov.b64 {%0, %1}, %2;" : "=f"(a), "=f"(b) : "l"(v));
}
__device__ __forceinline__ u64 fma2(u64 a, u64 b, u64 c) {
    u64 d; asm("fma.rn.f32x2 %0, %1, %2, %3;" : "=l"(d) : "l"(a), "l"(b), "l"(c)); return d;
}
__device__ __forceinline__ u64 add2(u64 a, u64 b) {
    u64 d; asm("add.rn.f32x2 %0, %1, %2;" : "=l"(d) : "l"(a), "l"(b)); return d;
}

__device__ __forceinline__ float sigf(float x) {
    return __fdividef(1.0f, 1.0f + __expf(-x));
}
__device__ __forceinline__ float spf(float x) {  // stable softplus
    return fmaxf(x, 0.0f) + __logf(1.0f + __expf(-fabsf(x)));
}

// ================= K1: node projections h_src / h_dst =================
// warp per node; lane t owns channels [4t, 4t+4). f32x2 FMAs.
__global__ void k_node_proj(const float* __restrict__ nf,
                            const float* __restrict__ Wsrc, const float* __restrict__ bsrc,
                            const float* __restrict__ Wdst, const float* __restrict__ bdst,
                            int N)
{
    extern __shared__ float sm[];
    float* smWs = sm;                 // 64*128 floats
    float* smWd = sm + NF * C;        // 64*128 floats
    float* smX  = sm + 2 * NF * C;    // 8*64 floats

    int tid = threadIdx.x;
    for (int i = tid; i < NF * C; i += blockDim.x) { smWs[i] = Wsrc[i]; smWd[i] = Wdst[i]; }

    int warp = tid >> 5, lane = tid & 31;
    float4 bs4 = *(const float4*)(bsrc + 4 * lane);
    float4 bd4 = *(const float4*)(bdst + 4 * lane);
    u64 bs_lo = pack2(bs4.x, bs4.y), bs_hi = pack2(bs4.z, bs4.w);
    u64 bd_lo = pack2(bd4.x, bd4.y), bd_hi = pack2(bd4.z, bd4.w);

    const float4* Ws4 = (const float4*)smWs;
    const float4* Wd4 = (const float4*)smWd;

    for (int tile = blockIdx.x; tile * 8 < N; tile += gridDim.x) {
        __syncthreads();
        int base = tile * 8;
        for (int i = tid; i < 8 * NF; i += blockDim.x) {
            int n = base + (i >> 6);
            smX[i] = (n < N) ? nf[(size_t)n * NF + (i & 63)] : 0.0f;
        }
        __syncthreads();

        int n = base + warp;
        if (n < N) {
            u64 as_lo = bs_lo, as_hi = bs_hi, ad_lo = bd_lo, ad_hi = bd_hi;
            const float4* X4 = (const float4*)(smX + warp * NF);
            #pragma unroll
            for (int kk = 0; kk < NF / 4; ++kk) {
                float4 xv = X4[kk];
                u64 xx[4] = { pack2(xv.x, xv.x), pack2(xv.y, xv.y),
                              pack2(xv.z, xv.z), pack2(xv.w, xv.w) };
                #pragma unroll
                for (int j = 0; j < 4; ++j) {
                    F4U ws; ws.f = Ws4[(kk * 4 + j) * 32 + lane];
                    as_lo = fma2(xx[j], ws.u[0], as_lo);
                    as_hi = fma2(xx[j], ws.u[1], as_hi);
                    F4U wd; wd.f = Wd4[(kk * 4 + j) * 32 + lane];
                    ad_lo = fma2(xx[j], wd.u[0], ad_lo);
                    ad_hi = fma2(xx[j], wd.u[1], ad_hi);
                }
            }
            F4U o;
            o.u[0] = as_lo; o.u[1] = as_hi;
            *(float4*)(g_hsrc + (size_t)n * C + 4 * lane) = o.f;
            o.u[0] = ad_lo; o.u[1] = ad_hi;
            *(float4*)(g_hdst + (size_t)n * C + 4 * lane) = o.f;
        }
    }
}

// ================= K2: edge GEMM + gathers -> m, plus BN stats =================
// 2 edges per warp share the smem W loads; lane t owns channels [4t, 4t+4).
__global__ void k_edge_pass1(const float* __restrict__ ef,
                             const float* __restrict__ We, const float* __restrict__ be,
                             const int* __restrict__ src, const int* __restrict__ dst,
                             int E)
{
    __shared__ __align__(16) float smW[EF * C];     // 16 KB
    __shared__ __align__(16) float smX[16 * EF];    // 2 KB
    __shared__ int   smS[16], smD[16];
    __shared__ float smRed[2 * C];

    int tid = threadIdx.x;
    for (int i = tid; i < EF * C; i += blockDim.x) smW[i] = We[i];

    int warp = tid >> 5, lane = tid & 31;
    float4 b4 = *(const float4*)(be + 4 * lane);
    u64 b_lo = pack2(b4.x, b4.y), b_hi = pack2(b4.z, b4.w);

    u64 s_lo = 0ull, s_hi = 0ull, q_lo = 0ull, q_hi = 0ull;  // {0f,0f} == 0ull

    const float4* W4 = (const float4*)smW;

    for (int tile = blockIdx.x; tile * 16 < E; tile += gridDim.x) {
        __syncthreads();
        int ebase = tile * 16;
        for (int i = tid; i < 16 * EF; i += blockDim.x) {
            int e = ebase + (i >> 5);
            smX[i] = (e < E) ? ef[(size_t)e * EF + (i & 31)] : 0.0f;
        }
        if (tid < 16)            { int e = ebase + tid;        smS[tid]      = (e < E) ? src[e] : 0; }
        else if (tid < 32)       { int e = ebase + (tid - 16); smD[tid - 16] = (e < E) ? dst[e] : 0; }
        __syncthreads();

        int e0 = ebase + 2 * warp, e1 = e0 + 1;
        u64 a0l = b_lo, a0h = b_hi, a1l = b_lo, a1h = b_hi;
        const float4* X0 = (const float4*)(smX + (2 * warp) * EF);
        const float4* X1 = (const float4*)(smX + (2 * warp + 1) * EF);

        #pragma unroll
        for (int kk = 0; kk < EF / 4; ++kk) {
            float4 xv0 = X0[kk], xv1 = X1[kk];
            u64 x0[4] = { pack2(xv0.x, xv0.x), pack2(xv0.y, xv0.y),
                          pack2(xv0.z, xv0.z), pack2(xv0.w, xv0.w) };
            u64 x1[4] = { pack2(xv1.x, xv1.x), pack2(xv1.y, xv1.y),
                          pack2(xv1.z, xv1.z), pack2(xv1.w, xv1.w) };
            #pragma unroll
            for (int j = 0; j < 4; ++j) {
                F4U w; w.f = W4[(kk * 4 + j) * 32 + lane];
                a0l = fma2(x0[j], w.u[0], a0l);
                a0h = fma2(x0[j], w.u[1], a0h);
                a1l = fma2(x1[j], w.u[0], a1l);
                a1h = fma2(x1[j], w.u[1], a1h);
            }
        }

        if (e0 < E) {
            int s = smS[2 * warp], d = smD[2 * warp];
            F4U hs, hd;
            hs.f = *(const float4*)(g_hsrc + (size_t)s * C + 4 * lane);
            hd.f = *(const float4*)(g_hdst + (size_t)d * C + 4 * lane);
            a0l = add2(add2(a0l, hs.u[0]), hd.u[0]);
            a0h = add2(add2(a0h, hs.u[1]), hd.u[1]);
            F4U m; m.u[0] = a0l; m.u[1] = a0h;
            *(float4*)(g_m + (size_t)e0 * C + 4 * lane) = m.f;
            s_lo = add2(s_lo, a0l); s_hi = add2(s_hi, a0h);
            q_lo = fma2(a0l, a0l, q_lo); q_hi = fma2(a0h, a0h, q_hi);
        }
        if (e1 < E) {
            int s = smS[2 * warp + 1], d = smD[2 * warp + 1];
            F4U hs, hd;
            hs.f = *(const float4*)(g_hsrc + (size_t)s * C + 4 * lane);
            hd.f = *(const float4*)(g_hdst + (size_t)d * C + 4 * lane);
            a1l = add2(add2(a1l, hs.u[0]), hd.u[0]);
            a1h = add2(add2(a1h, hs.u[1]), hd.u[1]);
            F4U m; m.u[0] = a1l; m.u[1] = a1h;
            *(float4*)(g_m + (size_t)e1 * C + 4 * lane) = m.f;
            s_lo = add2(s_lo, a1l); s_hi = add2(s_hi, a1h);
            q_lo = fma2(a1l, a1l, q_lo); q_hi = fma2(a1h, a1h, q_hi);
        }
    }

    // block-level BN-stat reduction
    __syncthreads();
    for (int i = tid; i < 2 * C; i += blockDim.x) smRed[i] = 0.0f;
    __syncthreads();
    float v0, v1, v2, v3;
    unpack2(s_lo, v0, v1); unpack2(s_hi, v2, v3);
    atomicAdd(&smRed[4 * lane + 0], v0); atomicAdd(&smRed[4 * lane + 1], v1);
    atomicAdd(&smRed[4 * lane + 2], v2); atomicAdd(&smRed[4 * lane + 3], v3);
    unpack2(q_lo, v0, v1); unpack2(q_hi, v2, v3);
    atomicAdd(&smRed[C + 4 * lane + 0], v0); atomicAdd(&smRed[C + 4 * lane + 1], v1);
    atomicAdd(&smRed[C + 4 * lane + 2], v2); atomicAdd(&smRed[C + 4 * lane + 3], v3);
    __syncthreads();
    if (tid < C) {
        atomicAdd(&g_sum[tid],   smRed[tid]);
        atomicAdd(&g_sumsq[tid], smRed[C + tid]);
    }
}

// ================= K3: finalize edge-BN scale/shift =================
__global__ void k_bn_m(const float* __restrict__ gamma, const float* __restrict__ beta, float invE)
{
    int t = threadIdx.x;  // 128 threads
    float mean = g_sum[t] * invE;
    float var  = fmaxf(g_sumsq[t] * invE - mean * mean, 0.0f);
    float s    = gamma[t] * rsqrtf(var + BN_EPS);
    g_bn_s[t] = s;
    g_bn_b[t] = beta[t] - mean * s;
}

// ================= K4: BN + sigmoid*softplus gate + scatter-add =================
// half-warp (16 lanes) per edge; lane-in-half h owns channels [4h, 4h+4).
__global__ void k_edge_pass2(const int* __restrict__ dst, int E)
{
    int lane = threadIdx.x & 31;
    int h    = lane & 15;
    int half = lane >> 4;
    long gw     = (long)blockIdx.x * (blockDim.x >> 5) + (threadIdx.x >> 5);
    long nwarps = (long)gridDim.x * (blockDim.x >> 5);

    float4 sA = *(const float4*)(g_bn_s + 4 * h);
    float4 bA = *(const float4*)(g_bn_b + 4 * h);
    float4 sB = *(const float4*)(g_bn_s + NF + 4 * h);
    float4 bB = *(const float4*)(g_bn_b + NF + 4 * h);

    for (long p = gw; p * 2 < E; p += nwarps) {
        long e = 2 * p + half;
        if (e < E) {
            int d = dst[e];
            float4 m1 = *(const float4*)(g_m + (size_t)e * C + 4 * h);
            float4 m2 = *(const float4*)(g_m + (size_t)e * C + NF + 4 * h);
            float a0 = fmaf(m1.x, sA.x, bA.x), a1 = fmaf(m1.y, sA.y, bA.y);
            float a2 = fmaf(m1.z, sA.z, bA.z), a3 = fmaf(m1.w, sA.w, bA.w);
            float g0 = fmaf(m2.x, sB.x, bB.x), g1 = fmaf(m2.y, sB.y, bB.y);
            float g2 = fmaf(m2.z, sB.z, bB.z), g3 = fmaf(m2.w, sB.w, bB.w);
            float y0 = sigf(a0) * spf(g0);
            float y1 = sigf(a1) * spf(g1);
            float y2 = sigf(a2) * spf(g2);
            float y3 = sigf(a3) * spf(g3);
            float* pd = g_h + (size_t)d * NF + 4 * h;
            asm volatile("red.global.add.v4.f32 [%0], {%1, %2, %3, %4};"
                         :: "l"(pd), "f"(y0), "f"(y1), "f"(y2), "f"(y3) : "memory");
        }
    }
}

// ================= K5: node-BN statistics =================
__global__ void k_node_stats(int N)
{
    __shared__ float smS[NF], smQ[NF];
    int tid = threadIdx.x;
    if (tid < NF) { smS[tid] = 0.0f; smQ[tid] = 0.0f; }
    __syncthreads();
    float s = 0.0f, q = 0.0f;
    long total  = (long)N * NF;
    long stride = (long)gridDim.x * blockDim.x;   // multiple of 64
    for (long i = (long)blockIdx.x * blockDim.x + tid; i < total; i += stride) {
        float v = g_h[i];
        s += v; q += v * v;
    }
    int c = tid & 63;
    atomicAdd(&smS[c], s);
    atomicAdd(&smQ[c], q);
    __syncthreads();
    if (tid < NF) {
        atomicAdd(&g_nsum[tid],   smS[tid]);
        atomicAdd(&g_nsumsq[tid], smQ[tid]);
    }
}

// ================= K6: node BN + residual + softplus =================
__global__ void k_final(const float* __restrict__ nf,
                        const float* __restrict__ gamma, const float* __restrict__ beta,
                        float* __restrict__ out, int N)
{
    __shared__ float sS[NF], sB[NF];
    int tid = threadIdx.x;
    if (tid < NF) {
        float invN = 1.0f / (float)N;
        float mean = g_nsum[tid] * invN;
        float var  = fmaxf(g_nsumsq[tid] * invN - mean * mean, 0.0f);
        float s    = gamma[tid] * rsqrtf(var + BN_EPS);
        sS[tid] = s;
        sB[tid] = beta[tid] - mean * s;
    }
    __syncthreads();
    long total  = (long)N * NF;
    long stride = (long)gridDim.x * blockDim.x;   // multiple of 64
    int  c = tid & 63;
    float s = sS[c], b = sB[c];
    for (long i = (long)blockIdx.x * blockDim.x + tid; i < total; i += stride) {
        float x = nf[i] + fmaf(g_h[i], s, b);
        out[i]  = fmaxf(x, 0.0f) + __logf(1.0f + __expf(-fabsf(x)));
    }
}

// ================= launch =================
extern "C" void kernel_launch(void* const* d_in, const int* in_sizes, int n_in,
                              void* d_out, int out_size)
{
    const float* node_feats = (const float*)d_in[0];
    const float* edge_feats = (const float*)d_in[1];
    const float* W_src   = (const float*)d_in[2];
    const float* b_src   = (const float*)d_in[3];
    const float* W_dst   = (const float*)d_in[4];
    const float* b_dst   = (const float*)d_in[5];
    const float* W_edge  = (const float*)d_in[6];
    const float* b_edge  = (const float*)d_in[7];
    const float* gamma_m = (const float*)d_in[8];
    const float* beta_m  = (const float*)d_in[9];
    const float* gamma_n = (const float*)d_in[10];
    const float* beta_n  = (const float*)d_in[11];
    const int*   src     = (const int*)d_in[12];
    const int*   dst     = (const int*)d_in[13];

    int N = in_sizes[0] / NF;
    int E = in_sizes[12];

    void *ph, *psum, *psumsq, *pnsum, *pnsumsq;
    cudaGetSymbolAddress(&ph, g_h);
    cudaGetSymbolAddress(&psum, g_sum);
    cudaGetSymbolAddress(&psumsq, g_sumsq);
    cudaGetSymbolAddress(&pnsum, g_nsum);
    cudaGetSymbolAddress(&pnsumsq, g_nsumsq);
    cudaMemsetAsync(ph, 0, (size_t)N * NF * sizeof(float));
    cudaMemsetAsync(psum, 0, C * sizeof(float));
    cudaMemsetAsync(psumsq, 0, C * sizeof(float));
    cudaMemsetAsync(pnsum, 0, NF * sizeof(float));
    cudaMemsetAsync(pnsumsq, 0, NF * sizeof(float));

    int smem1 = (2 * NF * C + 8 * NF) * (int)sizeof(float);   // 66 KB
    cudaFuncSetAttribute(k_node_proj, cudaFuncAttributeMaxDynamicSharedMemorySize, smem1);

    k_node_proj<<<1184, 256, smem1>>>(node_feats, W_src, b_src, W_dst, b_dst, N);
    k_edge_pass1<<<1184, 256>>>(edge_feats, W_edge, b_edge, src, dst, E);
    k_bn_m<<<1, 128>>>(gamma_m, beta_m, 1.0f / (float)E);
    k_edge_pass2<<<2368, 256>>>(dst, E);
    k_node_stats<<<512, 256>>>(N);
    k_final<<<512, 256>>>(node_feats, gamma_n, beta_n, (float*)d_out, N);
}

// round 11
// speedup vs baseline: 1.1403x; 1.1403x over previous
#include <cuda_runtime.h>
#include <stdint.h>

#define NF     64
#define C      128
#define EF     32
#define MAXN   100000
#define MAXE   1600000
#define BN_EPS 1e-5f

// ---------------- scratch (device globals; no allocations) ----------------
__device__ __align__(16) float g_hsrc[(size_t)MAXN * C];   // 51.2 MB
__device__ __align__(16) float g_hdst[(size_t)MAXN * C];   // 51.2 MB
__device__ __align__(16) float g_m[(size_t)MAXE * C];      // 819 MB
__device__ __align__(16) float g_h[(size_t)MAXN * NF];     // 25.6 MB
__device__ __align__(16) float g_sum[C];
__device__ __align__(16) float g_sumsq[C];
__device__ __align__(16) float g_bn_s[C];
__device__ __align__(16) float g_bn_b[C];
__device__ __align__(16) float g_nsum[NF];
__device__ __align__(16) float g_nsumsq[NF];

// ---------------- packed f32x2 helpers ----------------
typedef unsigned long long u64;
union F4U { float4 f; u64 u[2]; };

__device__ __forceinline__ u64 pack2(float a, float b) {
    u64 r; asm("mov.b64 %0, {%1, %2};" : "=l"(r) : "f"(a), "f"(b)); return r;
}
__device__ __forceinline__ void unpack2(u64 v, float& a, float& b) {
    asm("mov.b64 {%0, %1}, %2;" : "=f"(a), "=f"(b) : "l"(v));
}
__device__ __forceinline__ u64 fma2(u64 a, u64 b, u64 c) {
    u64 d; asm("fma.rn.f32x2 %0, %1, %2, %3;" : "=l"(d) : "l"(a), "l"(b), "l"(c)); return d;
}
__device__ __forceinline__ u64 add2(u64 a, u64 b) {
    u64 d; asm("add.rn.f32x2 %0, %1, %2;" : "=l"(d) : "l"(a), "l"(b)); return d;
}

__device__ __forceinline__ float sigf(float x) {
    return __fdividef(1.0f, 1.0f + __expf(-x));
}
__device__ __forceinline__ float spf(float x) {  // stable softplus
    return fmaxf(x, 0.0f) + __logf(1.0f + __expf(-fabsf(x)));
}

// ================= K1: node projections h_src / h_dst =================
// 4 nodes per warp share each W LDS; lane t owns channels [4t, 4t+4).
__global__ __launch_bounds__(256, 2)
void k_node_proj(const float* __restrict__ nf,
                 const float* __restrict__ Wsrc, const float* __restrict__ bsrc,
                 const float* __restrict__ Wdst, const float* __restrict__ bdst,
                 int N)
{
    extern __shared__ float sm[];
    float* smWs = sm;                 // 64*128 floats
    float* smWd = sm + NF * C;        // 64*128 floats
    float* smX  = sm + 2 * NF * C;    // 32 nodes * 64 floats

    int tid = threadIdx.x;
    for (int i = tid; i < NF * C; i += blockDim.x) { smWs[i] = Wsrc[i]; smWd[i] = Wdst[i]; }

    int warp = tid >> 5, lane = tid & 31;
    float4 bs4 = *(const float4*)(bsrc + 4 * lane);
    float4 bd4 = *(const float4*)(bdst + 4 * lane);
    u64 bs_lo = pack2(bs4.x, bs4.y), bs_hi = pack2(bs4.z, bs4.w);
    u64 bd_lo = pack2(bd4.x, bd4.y), bd_hi = pack2(bd4.z, bd4.w);

    const float4* Ws4 = (const float4*)smWs;
    const float4* Wd4 = (const float4*)smWd;
    const float4* ef4base = (const float4*)nf;

    for (int tile = blockIdx.x; tile * 32 < N; tile += gridDim.x) {
        __syncthreads();
        int nbase = tile * 32;
        // fill smX: 32 nodes * 16 float4 = 512 float4
        for (int i = tid; i < 32 * (NF / 4); i += blockDim.x) {
            int n = nbase + (i >> 4);
            float4 v = make_float4(0.f, 0.f, 0.f, 0.f);
            if (n < N) v = ef4base[(size_t)n * (NF / 4) + (i & 15)];
            ((float4*)smX)[i] = v;
        }
        __syncthreads();

        // warp handles nodes nbase + warp*4 + {0..3}
        u64 as_lo[4], as_hi[4], ad_lo[4], ad_hi[4];
        #pragma unroll
        for (int t = 0; t < 4; ++t) { as_lo[t] = bs_lo; as_hi[t] = bs_hi; ad_lo[t] = bd_lo; ad_hi[t] = bd_hi; }

        const float4* X4 = (const float4*)(smX + (warp * 4) * NF);

        #pragma unroll
        for (int kk = 0; kk < NF / 4; ++kk) {
            float4 xv[4];
            #pragma unroll
            for (int t = 0; t < 4; ++t) xv[t] = X4[t * (NF / 4) + kk];
            #pragma unroll
            for (int j = 0; j < 4; ++j) {
                F4U ws; ws.f = Ws4[(kk * 4 + j) * 32 + lane];
                F4U wd; wd.f = Wd4[(kk * 4 + j) * 32 + lane];
                #pragma unroll
                for (int t = 0; t < 4; ++t) {
                    float xs = ((const float*)&xv[t])[j];
                    u64 xx = pack2(xs, xs);
                    as_lo[t] = fma2(xx, ws.u[0], as_lo[t]);
                    as_hi[t] = fma2(xx, ws.u[1], as_hi[t]);
                    ad_lo[t] = fma2(xx, wd.u[0], ad_lo[t]);
                    ad_hi[t] = fma2(xx, wd.u[1], ad_hi[t]);
                }
            }
        }

        #pragma unroll
        for (int t = 0; t < 4; ++t) {
            int n = nbase + warp * 4 + t;
            if (n < N) {
                F4U o;
                o.u[0] = as_lo[t]; o.u[1] = as_hi[t];
                *(float4*)(g_hsrc + (size_t)n * C + 4 * lane) = o.f;
                o.u[0] = ad_lo[t]; o.u[1] = ad_hi[t];
                *(float4*)(g_hdst + (size_t)n * C + 4 * lane) = o.f;
            }
        }
    }
}

// ================= K2: edge GEMM + gathers -> m, plus BN stats =================
// 8 edges per warp share each W LDS; lane t owns channels [4t, 4t+4).
__global__ __launch_bounds__(256, 2)
void k_edge_pass1(const float* __restrict__ ef,
                  const float* __restrict__ We, const float* __restrict__ be,
                  const int* __restrict__ src, const int* __restrict__ dst,
                  int E)
{
    __shared__ __align__(16) float smW[EF * C];     // 16 KB
    __shared__ __align__(16) float smX[64 * EF];    // 8 KB
    __shared__ int   smS[64], smD[64];
    __shared__ float smRed[2 * C];

    int tid = threadIdx.x;
    for (int i = tid; i < EF * C; i += blockDim.x) smW[i] = We[i];

    int warp = tid >> 5, lane = tid & 31;
    float4 b4 = *(const float4*)(be + 4 * lane);
    u64 b_lo = pack2(b4.x, b4.y), b_hi = pack2(b4.z, b4.w);

    u64 s_lo = 0ull, s_hi = 0ull, q_lo = 0ull, q_hi = 0ull;  // {0f,0f} == 0ull

    const float4* W4 = (const float4*)smW;
    const float4* ef4 = (const float4*)ef;

    for (int tile = blockIdx.x; tile * 64 < E; tile += gridDim.x) {
        __syncthreads();
        int ebase = tile * 64;
        // fill smX: 64 edges * 8 float4 = 512 float4
        for (int i = tid; i < 64 * (EF / 4); i += blockDim.x) {
            int e = ebase + (i >> 3);
            float4 v = make_float4(0.f, 0.f, 0.f, 0.f);
            if (e < E) v = ef4[(size_t)e * (EF / 4) + (i & 7)];
            ((float4*)smX)[i] = v;
        }
        if (tid < 64)            { int e = ebase + tid;        smS[tid]      = (e < E) ? src[e] : 0; }
        else if (tid < 128)      { int e = ebase + (tid - 64); smD[tid - 64] = (e < E) ? dst[e] : 0; }
        __syncthreads();

        // warp handles edges ebase + warp*8 + {0..7}
        u64 a_lo[8], a_hi[8];
        #pragma unroll
        for (int t = 0; t < 8; ++t) { a_lo[t] = b_lo; a_hi[t] = b_hi; }

        const float4* X4 = (const float4*)(smX + (warp * 8) * EF);

        #pragma unroll
        for (int kk = 0; kk < EF / 4; ++kk) {
            float4 xv[8];
            #pragma unroll
            for (int t = 0; t < 8; ++t) xv[t] = X4[t * (EF / 4) + kk];
            #pragma unroll
            for (int j = 0; j < 4; ++j) {
                F4U w; w.f = W4[(kk * 4 + j) * 32 + lane];
                #pragma unroll
                for (int t = 0; t < 8; ++t) {
                    float xs = ((const float*)&xv[t])[j];
                    u64 xx = pack2(xs, xs);
                    a_lo[t] = fma2(xx, w.u[0], a_lo[t]);
                    a_hi[t] = fma2(xx, w.u[1], a_hi[t]);
                }
            }
        }

        #pragma unroll
        for (int t = 0; t < 8; ++t) {
            int e = ebase + warp * 8 + t;
            if (e < E) {
                int s = smS[warp * 8 + t], d = smD[warp * 8 + t];
                F4U hs, hd;
                hs.f = *(const float4*)(g_hsrc + (size_t)s * C + 4 * lane);
                hd.f = *(const float4*)(g_hdst + (size_t)d * C + 4 * lane);
                u64 lo = add2(add2(a_lo[t], hs.u[0]), hd.u[0]);
                u64 hi = add2(add2(a_hi[t], hs.u[1]), hd.u[1]);
                F4U m; m.u[0] = lo; m.u[1] = hi;
                __stcs((float4*)(g_m + (size_t)e * C + 4 * lane), m.f);   // streaming: keep L2 for tables
                s_lo = add2(s_lo, lo); s_hi = add2(s_hi, hi);
                q_lo = fma2(lo, lo, q_lo); q_hi = fma2(hi, hi, q_hi);
            }
        }
    }

    // block-level BN-stat reduction
    __syncthreads();
    for (int i = tid; i < 2 * C; i += blockDim.x) smRed[i] = 0.0f;
    __syncthreads();
    float v0, v1, v2, v3;
    unpack2(s_lo, v0, v1); unpack2(s_hi, v2, v3);
    atomicAdd(&smRed[4 * lane + 0], v0); atomicAdd(&smRed[4 * lane + 1], v1);
    atomicAdd(&smRed[4 * lane + 2], v2); atomicAdd(&smRed[4 * lane + 3], v3);
    unpack2(q_lo, v0, v1); unpack2(q_hi, v2, v3);
    atomicAdd(&smRed[C + 4 * lane + 0], v0); atomicAdd(&smRed[C + 4 * lane + 1], v1);
    atomicAdd(&smRed[C + 4 * lane + 2], v2); atomicAdd(&smRed[C + 4 * lane + 3], v3);
    __syncthreads();
    if (tid < C) {
        atomicAdd(&g_sum[tid],   smRed[tid]);
        atomicAdd(&g_sumsq[tid], smRed[C + tid]);
    }
}

// ================= K3: finalize edge-BN scale/shift =================
__global__ void k_bn_m(const float* __restrict__ gamma, const float* __restrict__ beta, float invE)
{
    int t = threadIdx.x;  // 128 threads
    float mean = g_sum[t] * invE;
    float var  = fmaxf(g_sumsq[t] * invE - mean * mean, 0.0f);
    float s    = gamma[t] * rsqrtf(var + BN_EPS);
    g_bn_s[t] = s;
    g_bn_b[t] = beta[t] - mean * s;
}

// ================= K4: BN + sigmoid*softplus gate + scatter-add =================
// half-warp (16 lanes) per edge; lane-in-half h owns channels [4h, 4h+4).
__global__ void k_edge_pass2(const int* __restrict__ dst, int E)
{
    int lane = threadIdx.x & 31;
    int h    = lane & 15;
    int half = lane >> 4;
    long gw     = (long)blockIdx.x * (blockDim.x >> 5) + (threadIdx.x >> 5);
    long nwarps = (long)gridDim.x * (blockDim.x >> 5);

    float4 sA = *(const float4*)(g_bn_s + 4 * h);
    float4 bA = *(const float4*)(g_bn_b + 4 * h);
    float4 sB = *(const float4*)(g_bn_s + NF + 4 * h);
    float4 bB = *(const float4*)(g_bn_b + NF + 4 * h);

    for (long p = gw; p * 2 < E; p += nwarps) {
        long e = 2 * p + half;
        if (e < E) {
            int d = dst[e];
            float4 m1 = __ldcs((const float4*)(g_m + (size_t)e * C + 4 * h));
            float4 m2 = __ldcs((const float4*)(g_m + (size_t)e * C + NF + 4 * h));
            float a0 = fmaf(m1.x, sA.x, bA.x), a1 = fmaf(m1.y, sA.y, bA.y);
            float a2 = fmaf(m1.z, sA.z, bA.z), a3 = fmaf(m1.w, sA.w, bA.w);
            float g0 = fmaf(m2.x, sB.x, bB.x), g1 = fmaf(m2.y, sB.y, bB.y);
            float g2 = fmaf(m2.z, sB.z, bB.z), g3 = fmaf(m2.w, sB.w, bB.w);
            float y0 = sigf(a0) * spf(g0);
            float y1 = sigf(a1) * spf(g1);
            float y2 = sigf(a2) * spf(g2);
            float y3 = sigf(a3) * spf(g3);
            float* pd = g_h + (size_t)d * NF + 4 * h;
            asm volatile("red.global.add.v4.f32 [%0], {%1, %2, %3, %4};"
                         :: "l"(pd), "f"(y0), "f"(y1), "f"(y2), "f"(y3) : "memory");
        }
    }
}

// ================= K5: node-BN statistics =================
__global__ void k_node_stats(int N)
{
    __shared__ float smS[NF], smQ[NF];
    int tid = threadIdx.x;
    if (tid < NF) { smS[tid] = 0.0f; smQ[tid] = 0.0f; }
    __syncthreads();
    float s = 0.0f, q = 0.0f;
    long total  = (long)N * NF;
    long stride = (long)gridDim.x * blockDim.x;   // multiple of 64
    for (long i = (long)blockIdx.x * blockDim.x + tid; i < total; i += stride) {
        float v = g_h[i];
        s += v; q += v * v;
    }
    int c = tid & 63;
    atomicAdd(&smS[c], s);
    atomicAdd(&smQ[c], q);
    __syncthreads();
    if (tid < NF) {
        atomicAdd(&g_nsum[tid],   smS[tid]);
        atomicAdd(&g_nsumsq[tid], smQ[tid]);
    }
}

// ================= K6: node BN + residual + softplus =================
__global__ void k_final(const float* __restrict__ nf,
                        const float* __restrict__ gamma, const float* __restrict__ beta,
                        float* __restrict__ out, int N)
{
    __shared__ float sS[NF], sB[NF];
    int tid = threadIdx.x;
    if (tid < NF) {
        float invN = 1.0f / (float)N;
        float mean = g_nsum[tid] * invN;
        float var  = fmaxf(g_nsumsq[tid] * invN - mean * mean, 0.0f);
        float s    = gamma[tid] * rsqrtf(var + BN_EPS);
        sS[tid] = s;
        sB[tid] = beta[tid] - mean * s;
    }
    __syncthreads();
    long total  = (long)N * NF;
    long stride = (long)gridDim.x * blockDim.x;   // multiple of 64
    int  c = tid & 63;
    float s = sS[c], b = sB[c];
    for (long i = (long)blockIdx.x * blockDim.x + tid; i < total; i += stride) {
        float x = nf[i] + fmaf(g_h[i], s, b);
        out[i]  = fmaxf(x, 0.0f) + __logf(1.0f + __expf(-fabsf(x)));
    }
}

// ================= launch =================
extern "C" void kernel_launch(void* const* d_in, const int* in_sizes, int n_in,
                              void* d_out, int out_size)
{
    const float* node_feats = (const float*)d_in[0];
    const float* edge_feats = (const float*)d_in[1];
    const float* W_src   = (const float*)d_in[2];
    const float* b_src   = (const float*)d_in[3];
    const float* W_dst   = (const float*)d_in[4];
    const float* b_dst   = (const float*)d_in[5];
    const float* W_edge  = (const float*)d_in[6];
    const float* b_edge  = (const float*)d_in[7];
    const float* gamma_m = (const float*)d_in[8];
    const float* beta_m  = (const float*)d_in[9];
    const float* gamma_n = (const float*)d_in[10];
    const float* beta_n  = (const float*)d_in[11];
    const int*   src     = (const int*)d_in[12];
    const int*   dst     = (const int*)d_in[13];

    int N = in_sizes[0] / NF;
    int E = in_sizes[12];

    void *ph, *psum, *psumsq, *pnsum, *pnsumsq;
    cudaGetSymbolAddress(&ph, g_h);
    cudaGetSymbolAddress(&psum, g_sum);
    cudaGetSymbolAddress(&psumsq, g_sumsq);
    cudaGetSymbolAddress(&pnsum, g_nsum);
    cudaGetSymbolAddress(&pnsumsq, g_nsumsq);
    cudaMemsetAsync(ph, 0, (size_t)N * NF * sizeof(float));
    cudaMemsetAsync(psum, 0, C * sizeof(float));
    cudaMemsetAsync(psumsq, 0, C * sizeof(float));
    cudaMemsetAsync(pnsum, 0, NF * sizeof(float));
    cudaMemsetAsync(pnsumsq, 0, NF * sizeof(float));

    int smem1 = (2 * NF * C + 32 * NF) * (int)sizeof(float);   // 64 KB + 8 KB
    cudaFuncSetAttribute(k_node_proj, cudaFuncAttributeMaxDynamicSharedMemorySize, smem1);

    k_node_proj<<<1184, 256, smem1>>>(node_feats, W_src, b_src, W_dst, b_dst, N);
    k_edge_pass1<<<1184, 256>>>(edge_feats, W_edge, b_edge, src, dst, E);
    k_bn_m<<<1, 128>>>(gamma_m, beta_m, 1.0f / (float)E);
    k_edge_pass2<<<2368, 256>>>(dst, E);
    k_node_stats<<<512, 256>>>(N);
    k_final<<<512, 256>>>(node_feats, gamma_n, beta_n, (float*)d_out, N);
}